// round 17
// baseline (speedup 1.0000x reference)
#include <cuda_runtime.h>
#include <cstdint>

#define NBATCH 4
#define SEQ    4096
#define DIM    128
#define MTOT   (NBATCH*SEQ)
#define QT     64
#define KT     192
#define CKA    96

__device__ float g_q[MTOT*DIM];
__device__ float g_k[MTOT*DIM];
__device__ float g_v[MTOT*DIM];
__device__ float g_mlpp[MTOT*DIM];          // x @ Wu[0:128] partial
__device__ float g_vsum_p[NBATCH*64*DIM];

// ---------------------------------------------------------------------------
__device__ __forceinline__ uint32_t hpack(float x0, float x1) {
    uint32_t r;
    asm("cvt.rn.f16x2.f32 %0, %1, %2;" : "=r"(r) : "f"(x1), "f"(x0));
    return r;
}
__device__ __forceinline__ float2 hunpack(uint32_t h) {
    float f0, f1;
    asm("{.reg .b16 lo,hi; mov.b32 {lo,hi}, %2; cvt.f32.f16 %0, lo; cvt.f32.f16 %1, hi;}"
        : "=f"(f0), "=f"(f1) : "r"(h));
    return make_float2(f0, f1);
}
__device__ __forceinline__ void hsplit2(float x0, float x1, uint32_t& h, uint32_t& l) {
    h = hpack(x0, x1);
    float2 hf = hunpack(h);
    l = hpack(x0 - hf.x, x1 - hf.y);
}
__device__ __forceinline__ void mma_f16(float* c, const uint32_t* a,
                                        uint32_t b0, uint32_t b1) {
    asm volatile(
        "mma.sync.aligned.m16n8k16.row.col.f32.f16.f16.f32 "
        "{%0,%1,%2,%3}, {%4,%5,%6,%7}, {%8,%9}, {%0,%1,%2,%3};"
        : "+f"(c[0]), "+f"(c[1]), "+f"(c[2]), "+f"(c[3])
        : "r"(a[0]), "r"(a[1]), "r"(a[2]), "r"(a[3]), "r"(b0), "r"(b1));
}

// ---------------------------------------------------------------------------
// GEMM core (BM=64, 512 threads): 64x128 tile, full K=128.
// A split hi/lo fp16; B staged directly from fp32 weights (hpack at STS),
// double-buffered.
// ---------------------------------------------------------------------------
#define GA_STR 68
#define GB_STR 136
#define GEMM_SMEM ((2*64*GA_STR + 2*64*GB_STR)*4)   // 104448 B

struct GemmH512 {
    uint32_t *Ah, *Al;
    uint32_t *Bbuf[2];

    __device__ void stage_A(const float* __restrict__ src, int m0, int tid) {
#pragma unroll
        for (int t = 0; t < 8; ++t) {
            int idx = tid + t*512;
            int row = idx >> 6, kp = idx & 63;
            float2 v = *(const float2*)(src + (size_t)(m0+row)*DIM + 2*kp);
            uint32_t h, l; hsplit2(v.x, v.y, h, l);
            Ah[row*GA_STR + kp] = h; Al[row*GA_STR + kp] = l;
        }
    }
    // stage B directly from fp32 weight rows [2kp][n], [2kp+1][n]
    __device__ void stage_Bd(int buf, const float* __restrict__ W, int tid) {
        uint32_t* dst = Bbuf[buf];
#pragma unroll
        for (int t = 0; t < 4; ++t) {
            int idx = tid + t*512;
            int kp = idx >> 5, n4 = (idx & 31)*4;
            float4 w0 = *(const float4*)(W + (size_t)(2*kp)*DIM + n4);
            float4 w1 = *(const float4*)(W + (size_t)(2*kp+1)*DIM + n4);
            *(uint4*)&dst[kp*GB_STR + n4] = make_uint4(
                hpack(w0.x, w1.x), hpack(w0.y, w1.y),
                hpack(w0.z, w1.z), hpack(w0.w, w1.w));
        }
    }
    __device__ void run(float c[4][4], int buf, int tid, bool lo_term) {
        const uint32_t* Bh = Bbuf[buf];
        const int lane = tid & 31, wid = tid >> 5;
        const int grp = lane >> 2, qd = lane & 3;
        const int wm = (wid & 3) * 16, wn = (wid >> 2) * 32;
#pragma unroll
        for (int t = 0; t < 8; ++t) {
            int kp0 = 8*t;
            uint32_t ah[4], al[4];
            int r = (wm + grp)*GA_STR;
            ah[0] = Ah[r + kp0+qd];   ah[1] = Ah[r + 8*GA_STR + kp0+qd];
            ah[2] = Ah[r + kp0+qd+4]; ah[3] = Ah[r + 8*GA_STR + kp0+qd+4];
            if (lo_term) {
                al[0] = Al[r + kp0+qd];   al[1] = Al[r + 8*GA_STR + kp0+qd];
                al[2] = Al[r + kp0+qd+4]; al[3] = Al[r + 8*GA_STR + kp0+qd+4];
            }
#pragma unroll
            for (int ni = 0; ni < 4; ++ni) {
                int col = wn + ni*8 + grp;
                uint32_t bh0 = Bh[(kp0+qd)*GB_STR + col];
                uint32_t bh1 = Bh[(kp0+qd+4)*GB_STR + col];
                mma_f16(c[ni], ah, bh0, bh1);
                if (lo_term) mma_f16(c[ni], al, bh0, bh1);
            }
        }
    }
};

// ---------------------------------------------------------------------------
// QKV+MLPx fused (BM=64, 512 thr): stage x once, loop Wq/Wk/Wu0/Wv with
// double-buffered B. V single-term; V phase also emits column sums.
// ---------------------------------------------------------------------------
__global__ __launch_bounds__(512, 2)
void qkv4_mma(const float* __restrict__ x,  const float* __restrict__ Wq,
              const float* __restrict__ Wk, const float* __restrict__ Wv,
              const float* __restrict__ Wu)
{
    extern __shared__ uint32_t smu[];
    GemmH512 g;
    g.Ah = smu;                    g.Al = g.Ah + 64*GA_STR;
    g.Bbuf[0] = g.Al + 64*GA_STR;  g.Bbuf[1] = g.Bbuf[0] + 64*GB_STR;

    const int tid = threadIdx.x;
    const int m0 = blockIdx.x * 64;

    const int lane = tid & 31, wid = tid >> 5;
    const int grp = lane >> 2, qd = lane & 3;
    const int wm = (wid & 3) * 16, wn = (wid >> 2) * 32;

    const float* Wtab[4] = {Wq, Wk, Wu, Wv};   // Wu rows 0..127 = first half

    g.stage_A(x, m0, tid);
    g.stage_Bd(0, Wtab[0], tid);
    __syncthreads();

    float c[4][4];
#pragma unroll 1
    for (int w = 0; w < 4; ++w) {
        if (w < 3) g.stage_Bd((w+1)&1, Wtab[w+1], tid);   // prefetch next
#pragma unroll
        for (int ni = 0; ni < 4; ++ni)
#pragma unroll
            for (int e = 0; e < 4; ++e) c[ni][e] = 0.f;
        g.run(c, w & 1, tid, w < 3);     // V projection single-term

        float* outp = (w == 0) ? g_q : (w == 1) ? g_k : (w == 2) ? g_mlpp : g_v;
#pragma unroll
        for (int ni = 0; ni < 4; ++ni) {
            size_t r0 = (size_t)(m0 + wm + grp);
            int col = wn + ni*8 + 2*qd;
            *(float2*)(outp + r0*DIM + col)     = make_float2(c[ni][0], c[ni][1]);
            *(float2*)(outp + (r0+8)*DIM + col) = make_float2(c[ni][2], c[ni][3]);
        }
        __syncthreads();      // next buffer staged + current reads done
    }

    // ---- V column partial sums (c holds the V tile) ----
    float* Ys = (float*)smu;                 // [64][132]
#pragma unroll
    for (int ni = 0; ni < 4; ++ni) {
        int r0 = wm + grp;
        int col = wn + ni*8 + 2*qd;
        Ys[r0*132 + col]         = c[ni][0];
        Ys[r0*132 + col + 1]     = c[ni][1];
        Ys[(r0+8)*132 + col]     = c[ni][2];
        Ys[(r0+8)*132 + col + 1] = c[ni][3];
    }
    __syncthreads();
    {
        int col = tid & 127, q = tid >> 7;   // q: 0..3
        float s = 0.f;
#pragma unroll
        for (int r = 0; r < 16; r += 4) {
            s += Ys[(q*16 + r+0)*132 + col];
            s += Ys[(q*16 + r+1)*132 + col];
            s += Ys[(q*16 + r+2)*132 + col];
            s += Ys[(q*16 + r+3)*132 + col];
        }
        float* ps2 = Ys + 64*132;
        ps2[q*128 + col] = s;
        __syncthreads();
        if (tid < 128) {
            int b = m0 >> 12;
            int t = (m0 >> 6) & 63;
            g_vsum_p[(b*64 + t)*128 + tid] =
                (ps2[tid] + ps2[128 + tid]) + (ps2[256 + tid] + ps2[384 + tid]);
        }
    }
}

// ---------------------------------------------------------------------------
// Attention + fused MLP tail + LN. 64-query tile, 256 threads.
// ---------------------------------------------------------------------------
#define AQ_STR 68
#define AK_STR 68
#define AV_STR 136
#define AP_STR 196
#define PH_STR 100
#define Q_WORDS  (QT*AQ_STR)        // 4352 per array
#define KV_WORDS (CKA*AK_STR)       // 6528
#define P_WORDS  (QT*AP_STR)        // 12544
#define ATTN_SMEM ((2*Q_WORDS + KV_WORDS + P_WORDS)*4 + (KT+QT)*4 + 128*4)

__global__ __launch_bounds__(256, 2)
void attn_mma(const int* __restrict__ mask, const float* __restrict__ x,
              const float* __restrict__ Wu, const float* __restrict__ bu,
              const float* __restrict__ gamma, const float* __restrict__ beta,
              float* __restrict__ out)
{
    extern __shared__ uint32_t smu[];
    uint32_t* Qh = smu;
    uint32_t* Ql = Qh + Q_WORDS;
    uint32_t* KV = Ql + Q_WORDS;
    float*    Ps = (float*)(KV + KV_WORDS);
    int*     msk = (int*)(Ps + P_WORDS);
    int*     qmk = msk + KT;
    float* vsum_s = (float*)(qmk + QT);   // [128]

    uint32_t* Ks = KV;
    uint32_t* Vs = KV;
    uint32_t* Ph = Qh;                    // packed fp16 P, overlays Q
    uint32_t* Ag = KV;                    // packed fp16 agg [64][68], overlays K/V
    uint32_t* Wu1 = (uint32_t*)Ps;        // Wu second half [64][136], overlays Ps
    float*    Yf = (float*)Qh;            // fused Y [64][132], overlays Q/P

    const int tid = threadIdx.x;
    const int b  = blockIdx.y;
    const int q0 = blockIdx.x * QT;
    const int kbase = q0 - 64;

    if (tid < KT) {
        int j = kbase + tid;
        msk[tid] = (j >= 0 && j < SEQ) ? mask[b*SEQ + j] : 0;
    }
    if (tid < QT) qmk[tid] = mask[b*SEQ + q0 + tid];

#pragma unroll
    for (int t = 0; t < 16; ++t) {
        int idx = tid + t*256;
        int row = idx >> 6, kp = idx & 63;
        float2 v = *(const float2*)(g_q + ((size_t)b*SEQ + q0 + row)*DIM + 2*kp);
        uint32_t h, l; hsplit2(v.x, v.y, h, l);
        Qh[row*AQ_STR + kp] = h; Ql[row*AQ_STR + kp] = l;
    }
#pragma unroll
    for (int t = 0; t < 24; ++t) {
        int idx = tid + t*256;
        int row = idx >> 6, kp = idx & 63;
        int j = kbase + row;
        uint32_t h = 0;
        if (j >= 0 && j < SEQ) {
            float2 v = *(const float2*)(g_k + ((size_t)b*SEQ + j)*DIM + 2*kp);
            h = hpack(v.x, v.y);
        }
        Ks[row*AK_STR + kp] = h;
    }
    __syncthreads();

    int need_vsum = __syncthreads_or((tid < QT) ? (qmk[tid] == 0) : 0);
    if (need_vsum && tid < 128) {
        float s = 0.f;
#pragma unroll 4
        for (int t = 0; t < 64; ++t) s += g_vsum_p[(b*64 + t)*128 + tid];
        vsum_s[tid] = s * (1.f/(float)SEQ);
    }

    const int lane = tid & 31, wid = tid >> 5;
    const int grp = lane >> 2, qd = lane & 3;
    const float scale = 0.08838834764831845f;

    // ---- S = Q K^T, 2 chunks of 96 keys; warps 4(m) x 2(n), band skip ----
    {
        const int wm = (wid & 3) * 16;
        const int wn = (wid >> 2) * 48;
#pragma unroll 1
        for (int c = 0; c < 2; ++c) {
            float cs[6][4];
#pragma unroll
            for (int ni = 0; ni < 6; ++ni)
#pragma unroll
                for (int e = 0; e < 4; ++e) cs[ni][e] = 0.f;

            int cb = c*CKA + wn;
            bool skip = (cb + 47 < wm) || (cb > wm + 143);
            if (!skip) {
#pragma unroll
                for (int t = 0; t < 8; ++t) {
                    int kp0 = 8*t;
                    uint32_t ah[4], al[4];
                    int r = (wm + grp)*AQ_STR;
                    ah[0] = Qh[r + kp0+qd];   ah[1] = Qh[r + 8*AQ_STR + kp0+qd];
                    ah[2] = Qh[r + kp0+qd+4]; ah[3] = Qh[r + 8*AQ_STR + kp0+qd+4];
                    al[0] = Ql[r + kp0+qd];   al[1] = Ql[r + 8*AQ_STR + kp0+qd];
                    al[2] = Ql[r + kp0+qd+4]; al[3] = Ql[r + 8*AQ_STR + kp0+qd+4];
#pragma unroll
                    for (int ni = 0; ni < 6; ++ni) {
                        int col = (wn + ni*8 + grp)*AK_STR;
                        uint32_t bh0 = Ks[col + kp0+qd];
                        uint32_t bh1 = Ks[col + kp0+qd+4];
                        mma_f16(cs[ni], ah, bh0, bh1);
                        mma_f16(cs[ni], al, bh0, bh1);
                    }
                }
            }
#pragma unroll
            for (int ni = 0; ni < 6; ++ni) {
#pragma unroll
                for (int e = 0; e < 4; ++e) {
                    int qi = wm + grp + (e >> 1)*8;
                    int jg = cb + ni*8 + 2*qd + (e & 1);
                    bool valid = msk[jg] && (jg >= qi) && (jg <= qi + 128);
                    Ps[qi*AP_STR + jg] = valid ? cs[ni][e]*scale : -1e9f;
                }
            }
            __syncthreads();
            if (c == 0) {
#pragma unroll
                for (int t = 0; t < 24; ++t) {
                    int idx = tid + t*256;
                    int row = idx >> 6, kp = idx & 63;
                    int j = kbase + CKA + row;
                    uint32_t h = 0;
                    if (j >= 0 && j < SEQ) {
                        float2 v = *(const float2*)(g_k + ((size_t)b*SEQ + j)*DIM + 2*kp);
                        h = hpack(v.x, v.y);
                    }
                    Ks[row*AK_STR + kp] = h;
                }
                __syncthreads();
            }
        }
    }

    // stage V chunk 0
#pragma unroll
    for (int t = 0; t < 6; ++t) {
        int idx = tid + t*256;
        int kp = idx >> 5, c4 = (idx & 31)*4;
        int j0 = kbase + 2*kp, j1 = j0 + 1;
        float4 v0 = make_float4(0,0,0,0), v1 = make_float4(0,0,0,0);
        if (j0 >= 0 && j0 < SEQ) v0 = *(const float4*)(g_v + ((size_t)b*SEQ + j0)*DIM + c4);
        if (j1 >= 0 && j1 < SEQ) v1 = *(const float4*)(g_v + ((size_t)b*SEQ + j1)*DIM + c4);
        *(uint4*)&Vs[kp*AV_STR + c4] = make_uint4(
            hpack(v0.x, v1.x), hpack(v0.y, v1.y), hpack(v0.z, v1.z), hpack(v0.w, v1.w));
    }

    // softmax: 4 threads per row; pack normalized P into fp16 Ph
    {
        int qi = tid >> 2, lg = tid & 3;
        float mx = -3.4e38f;
        for (int j = lg; j < KT; j += 4) mx = fmaxf(mx, Ps[qi*AP_STR + j]);
        mx = fmaxf(mx, __shfl_xor_sync(0xffffffffu, mx, 1));
        mx = fmaxf(mx, __shfl_xor_sync(0xffffffffu, mx, 2));
        float s = 0.f;
        for (int j = lg; j < KT; j += 4) {
            float e = __expf(Ps[qi*AP_STR + j] - mx);
            Ps[qi*AP_STR + j] = e;
            s += e;
        }
        s += __shfl_xor_sync(0xffffffffu, s, 1);
        s += __shfl_xor_sync(0xffffffffu, s, 2);
        float inv = 1.f / s;
        for (int kp = lg; kp < CKA; kp += 4) {
            float e0 = Ps[qi*AP_STR + 2*kp];
            float e1 = Ps[qi*AP_STR + 2*kp + 1];
            Ph[qi*PH_STR + kp] = hpack(e0*inv, e1*inv);
        }
    }
    __syncthreads();

    // ---- agg = P V (single-term), 2 chunks of 48 key-pairs; warps 2m x 4n ----
    const int wm2 = (wid & 1) * 32;
    const int wn2 = (wid >> 1) * 32;
    float co[2][4][4];
#pragma unroll
    for (int mi = 0; mi < 2; ++mi)
#pragma unroll
        for (int ni = 0; ni < 4; ++ni)
#pragma unroll
            for (int e = 0; e < 4; ++e) co[mi][ni][e] = 0.f;

#pragma unroll 1
    for (int c = 0; c < 2; ++c) {
#pragma unroll
        for (int t = 0; t < 6; ++t) {
            int ck = c*48 + t*8;
            uint32_t ah[2][4];
#pragma unroll
            for (int mi = 0; mi < 2; ++mi) {
                int r = (wm2 + mi*16 + grp)*PH_STR + ck + qd;
                ah[mi][0] = Ph[r];
                ah[mi][1] = Ph[r + 8*PH_STR];
                ah[mi][2] = Ph[r + 4];
                ah[mi][3] = Ph[r + 8*PH_STR + 4];
            }
#pragma unroll
            for (int ni = 0; ni < 4; ++ni) {
                int col = wn2 + ni*8 + grp;
                uint32_t bh0 = Vs[(t*8+qd)*AV_STR + col];
                uint32_t bh1 = Vs[(t*8+qd+4)*AV_STR + col];
#pragma unroll
                for (int mi = 0; mi < 2; ++mi)
                    mma_f16(co[mi][ni], ah[mi], bh0, bh1);
            }
        }
        if (c == 0) {
            __syncthreads();
#pragma unroll
            for (int t = 0; t < 6; ++t) {
                int idx = tid + t*256;
                int kp = idx >> 5, c4 = (idx & 31)*4;
                int j0 = kbase + CKA + 2*kp, j1 = j0 + 1;
                float4 v0 = make_float4(0,0,0,0), v1 = make_float4(0,0,0,0);
                if (j0 >= 0 && j0 < SEQ) v0 = *(const float4*)(g_v + ((size_t)b*SEQ + j0)*DIM + c4);
                if (j1 >= 0 && j1 < SEQ) v1 = *(const float4*)(g_v + ((size_t)b*SEQ + j1)*DIM + c4);
                *(uint4*)&Vs[kp*AV_STR + c4] = make_uint4(
                    hpack(v0.x, v1.x), hpack(v0.y, v1.y), hpack(v0.z, v1.z), hpack(v0.w, v1.w));
            }
            __syncthreads();
        }
    }

    // ---- fused MLP tail ----
    __syncthreads();          // all PV reads of Vs/Ph done

    // pack agg into Ag [64][68]; masked rows get vsum
#pragma unroll
    for (int mi = 0; mi < 2; ++mi)
#pragma unroll
        for (int ni = 0; ni < 4; ++ni) {
            int kpc = (wn2 >> 1) + ni*4 + qd;
            int colc = wn2 + ni*8 + 2*qd;
#pragma unroll
            for (int half = 0; half < 2; ++half) {
                int qi = wm2 + mi*16 + grp + half*8;
                float v0 = co[mi][ni][half*2], v1 = co[mi][ni][half*2+1];
                if (!qmk[qi]) { v0 = vsum_s[colc]; v1 = vsum_s[colc + 1]; }
                Ag[qi*AQ_STR + kpc] = hpack(v0, v1);
            }
        }
    // stage Wu1 directly from fp32 Wu rows 128..255
#pragma unroll
    for (int t = 0; t < 8; ++t) {
        int idx = tid + t*256;
        int kp = idx >> 5, n4 = (idx & 31)*4;
        float4 w0 = *(const float4*)(Wu + (size_t)(128 + 2*kp)*DIM + n4);
        float4 w1 = *(const float4*)(Wu + (size_t)(129 + 2*kp)*DIM + n4);
        *(uint4*)&Wu1[kp*GB_STR + n4] = make_uint4(
            hpack(w0.x, w1.x), hpack(w0.y, w1.y), hpack(w0.z, w1.z), hpack(w0.w, w1.w));
    }
    __syncthreads();

    // GEMM: Y2 = Ag @ Wu1 (single-term), warps 2m x 4n
    float c2[2][4][4];
#pragma unroll
    for (int mi = 0; mi < 2; ++mi)
#pragma unroll
        for (int ni = 0; ni < 4; ++ni)
#pragma unroll
            for (int e = 0; e < 4; ++e) c2[mi][ni][e] = 0.f;
#pragma unroll
    for (int t = 0; t < 8; ++t) {
        int kp0 = 8*t;
        uint32_t ah[2][4];
#pragma unroll
        for (int mi = 0; mi < 2; ++mi) {
            int r = (wm2 + mi*16 + grp)*AQ_STR + kp0 + qd;
            ah[mi][0] = Ag[r];
            ah[mi][1] = Ag[r + 8*AQ_STR];
            ah[mi][2] = Ag[r + 4];
            ah[mi][3] = Ag[r + 8*AQ_STR + 4];
        }
#pragma unroll
        for (int ni = 0; ni < 4; ++ni) {
            int col = wn2 + ni*8 + grp;
            uint32_t bh0 = Wu1[(kp0+qd)*GB_STR + col];
            uint32_t bh1 = Wu1[(kp0+qd+4)*GB_STR + col];
#pragma unroll
            for (int mi = 0; mi < 2; ++mi)
                mma_f16(c2[mi][ni], ah[mi], bh0, bh1);
        }
    }
    __syncthreads();

    // epilogue: Y = relu(c2 + mlpp + bias), into Yf [64][132]
#pragma unroll
    for (int mi = 0; mi < 2; ++mi)
#pragma unroll
        for (int ni = 0; ni < 4; ++ni) {
            int r0 = wm2 + mi*16 + grp;
            int col = wn2 + ni*8 + 2*qd;
            float b0 = __ldg(bu + col), b1 = __ldg(bu + col + 1);
            size_t gr = (size_t)b*SEQ + q0 + r0;
            float2 p0 = *(const float2*)(g_mlpp + gr*DIM + col);
            float2 p1 = *(const float2*)(g_mlpp + (gr+8)*DIM + col);
            Yf[r0*132 + col]         = fmaxf(c2[mi][ni][0] + p0.x + b0, 0.f);
            Yf[r0*132 + col + 1]     = fmaxf(c2[mi][ni][1] + p0.y + b1, 0.f);
            Yf[(r0+8)*132 + col]     = fmaxf(c2[mi][ni][2] + p1.x + b0, 0.f);
            Yf[(r0+8)*132 + col + 1] = fmaxf(c2[mi][ni][3] + p1.y + b1, 0.f);
        }
    __syncthreads();

    // LN: 4 threads per row, 32 cols each
    {
        int row = tid >> 2;
        int part = tid & 3;
        size_t gr = (size_t)b*SEQ + q0 + row;
        const float* xr = x + gr*DIM + part*32;
        const float* yr = Yf + row*132 + part*32;
        float vals[32];
        float sum = 0.f, sq = 0.f;
#pragma unroll
        for (int j = 0; j < 8; ++j) {
            float4 xv = *(const float4*)(xr + j*4);
            float4 yv = *(const float4*)(yr + j*4);
            float v0 = yv.x+xv.x, v1 = yv.y+xv.y, v2 = yv.z+xv.z, v3 = yv.w+xv.w;
            vals[j*4+0]=v0; vals[j*4+1]=v1; vals[j*4+2]=v2; vals[j*4+3]=v3;
            sum += (v0+v1)+(v2+v3);
            sq  += (v0*v0+v1*v1)+(v2*v2+v3*v3);
        }
        sum += __shfl_xor_sync(0xffffffffu, sum, 1);
        sq  += __shfl_xor_sync(0xffffffffu, sq, 1);
        sum += __shfl_xor_sync(0xffffffffu, sum, 2);
        sq  += __shfl_xor_sync(0xffffffffu, sq, 2);
        float mu   = sum * (1.f/128.f);
        float var  = sq * (1.f/128.f) - mu*mu;
        float rstd = rsqrtf(var + 1e-5f);
        float* op = out + gr*DIM + part*32;
        const float* gp = gamma + part*32;
        const float* bp = beta + part*32;
#pragma unroll
        for (int j = 0; j < 8; ++j) {
            float4 gv = *(const float4*)(gp + j*4);
            float4 bv = *(const float4*)(bp + j*4);
            float4 o;
            o.x = gv.x*((vals[j*4+0]-mu)*rstd) + bv.x;
            o.y = gv.y*((vals[j*4+1]-mu)*rstd) + bv.y;
            o.z = gv.z*((vals[j*4+2]-mu)*rstd) + bv.z;
            o.w = gv.w*((vals[j*4+3]-mu)*rstd) + bv.w;
            *(float4*)(op + j*4) = o;
        }
    }
}

// ---------------------------------------------------------------------------
extern "C" void kernel_launch(void* const* d_in, const int* in_sizes, int n_in,
                              void* d_out, int out_size)
{
    const float* x    = (const float*)d_in[0];
    const int*   mask = (const int*)d_in[2];
    const float* Wq   = (const float*)d_in[3];
    const float* Wk   = (const float*)d_in[4];
    const float* Wv   = (const float*)d_in[5];
    const float* Wu   = (const float*)d_in[6];
    const float* bu   = (const float*)d_in[7];
    const float* gm   = (const float*)d_in[8];
    const float* bt   = (const float*)d_in[9];
    float* out = (float*)d_out;

    cudaFuncSetAttribute(qkv4_mma, cudaFuncAttributeMaxDynamicSharedMemorySize, GEMM_SMEM);
    cudaFuncSetAttribute(attn_mma, cudaFuncAttributeMaxDynamicSharedMemorySize, ATTN_SMEM);

    qkv4_mma<<<MTOT/64, 512, GEMM_SMEM>>>(x, Wq, Wk, Wv, Wu);
    attn_mma<<<dim3(SEQ/QT, NBATCH), 256, ATTN_SMEM>>>(mask, x, Wu, bu, gm, bt, out);
}